// round 12
// baseline (speedup 1.0000x reference)
#include <cuda_runtime.h>

// Quanvolution, 2 patches per thread, f32x2 lanes = (patchA, patchB).
// R12 (= R11 resubmitted after infra failure): persistent blocks — 784 CTAs x
// 4 tiles/thread (exact cover), cp.async double-buffered prefetch into shared
// (zero register cost), per-thread wait_group (no barriers). Tile stride
// 200704 = 98*2048 => batch advances by 2048/tile and (pp,pr,pj) are
// invariant: per-tile work is 2 pointer bumps. Compute body identical to R8:
// tan-form unnormalized RY butterflies (2 fma2, UR constants -> rt=2),
// K=prod-cos folded into Q, Gray-folded CNOT chains, MUFU encoding trig.
// Setup kernel + PDL as in R9.

#define NB    8192
#define PPB2  98
#define NTH   (NB * PPB2)            // 802,816
#define TPB   256
#define NBLK  784                    // 784*256*4 == NTH exactly
#define TSTRIDE 1605632              // floats per tile step: 2048 batches * 784

typedef unsigned long long u64;
typedef unsigned int u32;

// c_k[0..7]  = (+tan(par[k]/2)) dup'd f32x2
// c_k[8..15] = (-tan(par[k]/2)) dup'd f32x2
// c_k[16]    = (prod_k cos(par[k]/2)) dup'd f32x2
__constant__ u64 c_k[17];

static __device__ __forceinline__ u64 pk2(float lo, float hi) {
    u64 r; asm("mov.b64 %0, {%1, %2};" : "=l"(r) : "f"(lo), "f"(hi)); return r;
}
static __device__ __forceinline__ void upk2(u64 v, float& lo, float& hi) {
    asm("mov.b64 {%0, %1}, %2;" : "=f"(lo), "=f"(hi) : "l"(v));
}
static __device__ __forceinline__ u64 fma2(u64 a, u64 b, u64 c) {
    u64 d; asm("fma.rn.f32x2 %0, %1, %2, %3;" : "=l"(d) : "l"(a), "l"(b), "l"(c)); return d;
}
static __device__ __forceinline__ u64 mul2(u64 a, u64 b) {
    u64 d; asm("mul.rn.f32x2 %0, %1, %2;" : "=l"(d) : "l"(a), "l"(b)); return d;
}
static __device__ __forceinline__ u64 add2(u64 a, u64 b) {
    u64 d; asm("add.rn.f32x2 %0, %1, %2;" : "=l"(d) : "l"(a), "l"(b)); return d;
}
static __device__ __forceinline__ u64 sub2(u64 a, u64 b) {
    u64 d; asm("sub.rn.f32x2 %0, %1, %2;" : "=l"(d) : "l"(a), "l"(b)); return d;
}

static __device__ __forceinline__ void bf_tan(u64& lo, u64& hi, u64 pt, u64 nt) {
    u64 l1 = fma2(nt, hi, lo);
    hi     = fma2(pt, lo, hi);
    lo     = l1;
}

template<int BIT>
static __device__ __forceinline__ void ry_wire(u64 (&v)[16], u64 pt, u64 nt) {
    #pragma unroll
    for (int i = 0; i < 16; ++i)
        if (!(i & BIT))
            bf_tan(v[i], v[i | BIT], pt, nt);
}

static __device__ __forceinline__ void gray_perm(u64 (&v)[16]) {
    u64 t[16];
    #pragma unroll
    for (int i = 0; i < 16; ++i) t[i] = v[i ^ (i >> 1)];
    #pragma unroll
    for (int i = 0; i < 16; ++i) v[i] = t[i];
}

static __device__ __forceinline__ u32 smem_u32(const void* p) {
    u32 a;
    asm("{ .reg .u64 t; cvta.to.shared.u64 t, %1; cvt.u32.u64 %0, t; }" : "=r"(a) : "l"(p));
    return a;
}

#define CP16(SADDR, GPTR) \
    asm volatile("cp.async.ca.shared.global [%0], [%1], 16;" \
                 :: "r"(SADDR), "l"(GPTR) : "memory")
#define CP_COMMIT() asm volatile("cp.async.commit_group;" ::: "memory")
#define CP_WAIT(N)  asm volatile("cp.async.wait_group %0;" :: "n"(N) : "memory")

__global__ void setup_kernel(const float* __restrict__ par, u64* __restrict__ dst) {
    asm volatile("griddepcontrol.launch_dependents;");
    int lane = threadIdx.x;
    int k = lane & 7;
    float h = 0.5f * par[k];
    float s = sinf(h);
    float c = cosf(h);
    float t = s / c;
    float kp = c;
    kp *= __shfl_xor_sync(0xFFFFFFFFu, kp, 1);
    kp *= __shfl_xor_sync(0xFFFFFFFFu, kp, 2);
    kp *= __shfl_xor_sync(0xFFFFFFFFu, kp, 4);
    if (lane < 8) {
        dst[k]     = ((u64)__float_as_uint( t)) | ((u64)__float_as_uint( t) << 32);
        dst[8 + k] = ((u64)__float_as_uint(-t)) | ((u64)__float_as_uint(-t) << 32);
        if (lane == 0)
            dst[16] = ((u64)__float_as_uint(kp)) | ((u64)__float_as_uint(kp) << 32);
    }
}

// one (batch, patch-pair) tile: r0 = img row 2pr (A0 A1 B0 B1),
// r1 = img row 2pr+1 (A2 A3 B2 B3); writes 8 floats at op.
static __device__ __forceinline__ void compute_tile(float4 r0, float4 r1,
                                                    float* __restrict__ op)
{
    float h;
    h = 0.5f * r0.x; float cA0 = __cosf(h), sA0 = __sinf(h);
    h = 0.5f * r0.y; float cA1 = __cosf(h), sA1 = __sinf(h);
    h = 0.5f * r1.x; float cA2 = __cosf(h), sA2 = __sinf(h);
    h = 0.5f * r1.y; float cA3 = __cosf(h), sA3 = __sinf(h);
    h = 0.5f * r0.z; float cB0 = __cosf(h), sB0 = __sinf(h);
    h = 0.5f * r0.w; float cB1 = __cosf(h), sB1 = __sinf(h);
    h = 0.5f * r1.z; float cB2 = __cosf(h), sB2 = __sinf(h);
    h = 0.5f * r1.w; float cB3 = __cosf(h), sB3 = __sinf(h);

    u64 c0 = pk2(cA0, cB0), s0 = pk2(sA0, sB0);
    u64 c1 = pk2(cA1, cB1), s1 = pk2(sA1, sB1);
    u64 c2 = pk2(cA2, cB2), s2 = pk2(sA2, sB2);
    u64 c3 = pk2(cA3, cB3), s3 = pk2(sA3, sB3);

    // v[i] = P01[i0*2+i1] * Q[(i2^i1)*2 + (i3^i2)]  (first CNOT chain folded)
    u64 P01[4];
    P01[0] = mul2(c0, c1);
    P01[1] = mul2(c0, s1);
    P01[2] = mul2(s0, s1);
    P01[3] = mul2(s0, c1);

    // layer-1 wire-0 RY folded into P
    bf_tan(P01[0], P01[2], c_k[0], c_k[8]);
    bf_tan(P01[1], P01[3], c_k[0], c_k[8]);

    // normalization K = prod cos(par/2) folded into Q
    u64 Kc  = c_k[16];
    u64 c2K = mul2(c2, Kc);
    u64 s2K = mul2(s2, Kc);
    u64 Q[4];
    Q[0] = mul2(c2K, c3);
    Q[1] = mul2(c2K, s3);
    Q[2] = mul2(s2K, c3);
    Q[3] = mul2(s2K, s3);

    u64 v[16];
    #pragma unroll
    for (int i = 0; i < 16; ++i) {
        int i0 = (i >> 3) & 1, i1 = (i >> 2) & 1, i2 = (i >> 1) & 1, i3 = i & 1;
        v[i] = mul2(P01[i0 * 2 + i1], Q[(i2 ^ i1) * 2 + (i3 ^ i2)]);
    }

    ry_wire<4>(v, c_k[1], c_k[9]);
    ry_wire<2>(v, c_k[2], c_k[10]);
    ry_wire<1>(v, c_k[3], c_k[11]);
    gray_perm(v);
    ry_wire<8>(v, c_k[4], c_k[12]);
    ry_wire<4>(v, c_k[5], c_k[13]);
    ry_wire<2>(v, c_k[6], c_k[14]);
    ry_wire<1>(v, c_k[7], c_k[15]);
    // final CNOT chain folded into measurement signs (prefix parities)

    u64 p[16];
    #pragma unroll
    for (int i = 0; i < 16; ++i) p[i] = mul2(v[i], v[i]);

    u64 sa[8], da[8];
    #pragma unroll
    for (int k = 0; k < 8; ++k) {
        sa[k] = add2(p[2 * k], p[2 * k + 1]);
        da[k] = sub2(p[2 * k], p[2 * k + 1]);
    }
    u64 z3 = sub2(sub2(sub2(da[0], da[1]), sub2(da[2], da[3])),
                  sub2(sub2(da[4], da[5]), sub2(da[6], da[7])));

    u64 sb[4], e[4];
    #pragma unroll
    for (int j = 0; j < 4; ++j) {
        sb[j] = add2(sa[2 * j], sa[2 * j + 1]);
        e[j]  = sub2(sa[2 * j], sa[2 * j + 1]);
    }
    u64 z2 = sub2(sub2(e[0], e[1]), sub2(e[2], e[3]));

    u64 U0 = add2(sb[0], sb[1]), U1 = add2(sb[2], sb[3]);
    u64 E0 = sub2(sb[0], sb[1]), E1 = sub2(sb[2], sb[3]);
    u64 z1 = sub2(E0, E1);
    u64 z0 = sub2(U0, U1);

    float za0, zb0, za1, zb1, za2, zb2, za3, zb3;
    upk2(z0, za0, zb0); upk2(z1, za1, zb1);
    upk2(z2, za2, zb2); upk2(z3, za3, zb3);

    float4* o = reinterpret_cast<float4*>(op);
    o[0] = make_float4(za0, za1, za2, za3);
    o[1] = make_float4(zb0, zb1, zb2, zb3);
}

__global__ void __launch_bounds__(TPB)
quanv_kernel(const float* __restrict__ x, float* __restrict__ out)
{
    __shared__ float4 buf[2][TPB][2];   // 16 KB ping-pong, per-thread slots

    int tid = threadIdx.x;
    int gid = blockIdx.x * TPB + tid;   // tile-0 id; tiles: gid + it*200704
    int b0  = gid / PPB2;               // 0..2047
    int pp  = gid - b0 * PPB2;
    int pr  = pp / 7;
    int pj  = pp - pr * 7;
    // 200704 = 98*2048: per tile, batch += 2048; (pp,pr,pj) invariant.

    const float* ip = x   + b0 * 784 + pr * 56 + pj * 4;
    float*       op = out + b0 * 784 + pr * 56 + pj * 8;

    u32 sb0 = smem_u32(&buf[0][tid][0]);
    u32 sb1 = sb0 + (u32)(TPB * sizeof(float4) * 2);   // stage 1

    // prologue: prefetch tiles 0 and 1
    CP16(sb0,      ip);
    CP16(sb0 + 16, ip + 28);
    CP_COMMIT();
    CP16(sb1,      ip + TSTRIDE);
    CP16(sb1 + 16, ip + TSTRIDE + 28);
    CP_COMMIT();

    // tile 0 (stage 0); refill stage 0 with tile 2
    CP_WAIT(1);
    float4 r0 = buf[0][tid][0], r1 = buf[0][tid][1];
    CP16(sb0,      ip + 2 * TSTRIDE);
    CP16(sb0 + 16, ip + 2 * TSTRIDE + 28);
    CP_COMMIT();
    asm volatile("griddepcontrol.wait;" ::: "memory");   // c_k ready (PDL)
    compute_tile(r0, r1, op);

    // tile 1 (stage 1); refill stage 1 with tile 3
    CP_WAIT(1);
    r0 = buf[1][tid][0]; r1 = buf[1][tid][1];
    CP16(sb1,      ip + 3 * TSTRIDE);
    CP16(sb1 + 16, ip + 3 * TSTRIDE + 28);
    CP_COMMIT();
    compute_tile(r0, r1, op + TSTRIDE);

    // tile 2 (stage 0)
    CP_WAIT(1);
    r0 = buf[0][tid][0]; r1 = buf[0][tid][1];
    compute_tile(r0, r1, op + 2 * TSTRIDE);

    // tile 3 (stage 1)
    CP_WAIT(0);
    r0 = buf[1][tid][0]; r1 = buf[1][tid][1];
    compute_tile(r0, r1, op + 3 * TSTRIDE);
}

extern "C" void kernel_launch(void* const* d_in, const int* in_sizes, int n_in,
                              void* d_out, int out_size)
{
    const float* x   = (const float*)d_in[0];   // (8192,1,28,28) fp32
    const float* par = (const float*)d_in[1];   // (2,4) fp32
    float* out       = (float*)d_out;           // (8192, 784) fp32
    (void)in_sizes; (void)n_in; (void)out_size;

    void* ck_addr = nullptr;
    cudaGetSymbolAddress(&ck_addr, c_k);        // address query only — no alloc

    setup_kernel<<<1, 32>>>(par, (u64*)ck_addr);

    cudaLaunchConfig_t cfg = {};
    cfg.gridDim          = dim3(NBLK);
    cfg.blockDim         = dim3(TPB);
    cfg.dynamicSmemBytes = 0;
    cfg.stream           = 0;
    cudaLaunchAttribute attr[1];
    attr[0].id = cudaLaunchAttributeProgrammaticStreamSerialization;
    attr[0].val.programmaticStreamSerializationAllowed = 1;
    cfg.attrs    = attr;
    cfg.numAttrs = 1;
    cudaLaunchKernelEx(&cfg, quanv_kernel, x, out);
}